// round 1
// baseline (speedup 1.0000x reference)
#include <cuda_runtime.h>
#include <cuda_bf16.h>
#include <math.h>

#define T_DIM 4096
#define B_DIM 16
#define C_DIM 512
#define M_DIM (T_DIM * B_DIM)      // 65536
#define H_DIM 8
#define K_DIM 7
#define PAD_L 3
#define R_DIM (C_DIM / H_DIM)      // 64

// ---------------- scratch (no allocations allowed) ----------------
__device__ float g_y[(size_t)M_DIM * C_DIM];   // GEMM output (T,B,C) flattened, 128 MB
__device__ float g_wq[C_DIM * C_DIM];          // quantized weights
__device__ float g_wsm[H_DIM * K_DIM];         // softmaxed conv kernels

// ---------------- prep: quantize W + softmax(weight) ----------------
__global__ void prep_kernel(const float* __restrict__ W,
                            const float* __restrict__ conv_w) {
    int i = blockIdx.x * 256 + threadIdx.x;
    if (i < C_DIM * C_DIM) {
        float w = W[i];
        float a = fabsf(w) + 1e-12f;
        float e = rintf(log2f(a));          // rintf = round-half-to-even, matches jnp.round
        float q = copysignf(exp2f(e), w);
        g_wq[i] = (w == 0.0f) ? 0.0f : q;
    }
    if (blockIdx.x == 0 && threadIdx.x < H_DIM) {
        int h = threadIdx.x;
        float v[K_DIM];
        float m = -1e30f;
        #pragma unroll
        for (int k = 0; k < K_DIM; ++k) { v[k] = conv_w[h * K_DIM + k]; m = fmaxf(m, v[k]); }
        float s = 0.0f;
        #pragma unroll
        for (int k = 0; k < K_DIM; ++k) { v[k] = expf(v[k] - m); s += v[k]; }
        float inv = 1.0f / s;
        #pragma unroll
        for (int k = 0; k < K_DIM; ++k) g_wsm[h * K_DIM + k] = v[k] * inv;
    }
}

// ---------------- GEMM: y[m,d] = sum_c x[m,c]*Wq[d,c] + b[d] ----------------
// A = x (M x K, K-major), B = Wq (N x K, K-major) -> both coalesced on K.
// 128x128 block tile, BK=16, 256 threads, 8x8 microtile.
#define BM 128
#define BN 128
#define BK 16
#define SMEM_LD 132   // padded stride to avoid bank conflicts

__global__ __launch_bounds__(256) void gemm_kernel(const float* __restrict__ x,
                                                   const float* __restrict__ bias) {
    __shared__ float As[BK][SMEM_LD];
    __shared__ float Bs[BK][SMEM_LD];

    const int nb = blockIdx.x;       // 0..3
    const int mb = blockIdx.y;       // 0..511
    const int tid = threadIdx.x;
    const int tx = tid & 15;         // col group
    const int ty = tid >> 4;         // row group
    const int rowbase = ty * 8;
    const int colbase = tx * 8;

    float acc[8][8];
    #pragma unroll
    for (int i = 0; i < 8; ++i)
        #pragma unroll
        for (int j = 0; j < 8; ++j) acc[i][j] = 0.0f;

    const size_t a_base = (size_t)mb * BM * C_DIM;
    const size_t b_base = (size_t)nb * BN * C_DIM;

    for (int kt = 0; kt < C_DIM; kt += BK) {
        // load tiles: 128 rows x 16 cols = 512 float4, 2 per thread
        #pragma unroll
        for (int ld = 0; ld < 2; ++ld) {
            int idx = tid + ld * 256;          // 0..511
            int row = idx >> 2;
            int cv  = (idx & 3) * 4;
            float4 av = *(const float4*)&x[a_base + (size_t)row * C_DIM + kt + cv];
            As[cv + 0][row] = av.x;
            As[cv + 1][row] = av.y;
            As[cv + 2][row] = av.z;
            As[cv + 3][row] = av.w;
            float4 bv = *(const float4*)&g_wq[b_base + (size_t)row * C_DIM + kt + cv];
            Bs[cv + 0][row] = bv.x;
            Bs[cv + 1][row] = bv.y;
            Bs[cv + 2][row] = bv.z;
            Bs[cv + 3][row] = bv.w;
        }
        __syncthreads();

        #pragma unroll
        for (int k = 0; k < BK; ++k) {
            float a[8], bf[8];
            #pragma unroll
            for (int i = 0; i < 8; ++i) a[i]  = As[k][rowbase + i];
            #pragma unroll
            for (int j = 0; j < 8; ++j) bf[j] = Bs[k][colbase + j];
            #pragma unroll
            for (int i = 0; i < 8; ++i)
                #pragma unroll
                for (int j = 0; j < 8; ++j) acc[i][j] = fmaf(a[i], bf[j], acc[i][j]);
        }
        __syncthreads();
    }

    // epilogue: add bias, store to g_y
    float bs[8];
    #pragma unroll
    for (int j = 0; j < 8; ++j) bs[j] = bias[nb * BN + colbase + j];

    #pragma unroll
    for (int i = 0; i < 8; ++i) {
        size_t m = (size_t)mb * BM + rowbase + i;
        float* yrow = &g_y[m * C_DIM + nb * BN + colbase];
        #pragma unroll
        for (int j4 = 0; j4 < 2; ++j4) {
            float4 v;
            v.x = acc[i][j4 * 4 + 0] + bs[j4 * 4 + 0];
            v.y = acc[i][j4 * 4 + 1] + bs[j4 * 4 + 1];
            v.z = acc[i][j4 * 4 + 2] + bs[j4 * 4 + 2];
            v.w = acc[i][j4 * 4 + 3] + bs[j4 * 4 + 3];
            *(float4*)&yrow[j4 * 4] = v;
        }
    }
}

// ---------------- depthwise conv along time ----------------
#define TC 64

__global__ __launch_bounds__(512) void conv_kernel(float* __restrict__ out) {
    const int c  = threadIdx.x;            // 0..511
    const int b  = blockIdx.y;             // 0..15
    const int t0 = blockIdx.x * TC;
    const int h  = c >> 6;                 // c / R_DIM

    float w[K_DIM];
    #pragma unroll
    for (int k = 0; k < K_DIM; ++k) w[k] = g_wsm[h * K_DIM + k];

    float win[K_DIM];
    #pragma unroll
    for (int j = 0; j < K_DIM - 1; ++j) {
        int tt = t0 - PAD_L + j;
        win[j] = (tt >= 0 && tt < T_DIM)
                   ? g_y[((size_t)tt * B_DIM + b) * C_DIM + c] : 0.0f;
    }

    for (int t = t0; t < t0 + TC; ++t) {
        int tt = t + (K_DIM - 1 - PAD_L);
        win[K_DIM - 1] = (tt < T_DIM)
                   ? g_y[((size_t)tt * B_DIM + b) * C_DIM + c] : 0.0f;
        float acc = 0.0f;
        #pragma unroll
        for (int j = 0; j < K_DIM; ++j) acc = fmaf(w[j], win[j], acc);
        out[((size_t)t * B_DIM + b) * C_DIM + c] = acc;
        #pragma unroll
        for (int j = 0; j < K_DIM - 1; ++j) win[j] = win[j + 1];
    }
}

// ---------------- launch ----------------
extern "C" void kernel_launch(void* const* d_in, const int* in_sizes, int n_in,
                              void* d_out, int out_size) {
    const float* x       = (const float*)d_in[0];   // (T,B,C)
    const float* shift_W = (const float*)d_in[1];   // (C,C)
    const float* shift_b = (const float*)d_in[2];   // (C,)
    const float* weight  = (const float*)d_in[3];   // (H,K)
    float* out = (float*)d_out;

    prep_kernel<<<(C_DIM * C_DIM + 255) / 256, 256>>>(shift_W, weight);

    dim3 ggrid(C_DIM / BN, M_DIM / BM);   // (4, 512)
    gemm_kernel<<<ggrid, 256>>>(x, shift_b);

    dim3 cgrid(T_DIM / TC, B_DIM);        // (64, 16)
    conv_kernel<<<cgrid, 512>>>(out);
}

// round 3
// speedup vs baseline: 2.8320x; 2.8320x over previous
#include <cuda_runtime.h>
#include <cuda_bf16.h>
#include <math.h>
#include <stdint.h>

#define T_DIM 4096
#define B_DIM 16
#define C_DIM 512
#define M_DIM (T_DIM * B_DIM)      // 65536
#define H_DIM 8
#define K_DIM 7
#define PAD_L 3

// ---------------- scratch (no allocations allowed) ----------------
__device__ __align__(16) float g_y[(size_t)M_DIM * C_DIM];        // GEMM out, 128 MB
__device__ __align__(16) __nv_bfloat16 g_xhi[(size_t)M_DIM * C_DIM]; // 64 MB
__device__ __align__(16) __nv_bfloat16 g_xlo[(size_t)M_DIM * C_DIM]; // 64 MB
__device__ __align__(16) __nv_bfloat16 g_wqb[C_DIM * C_DIM];      // quantized W, bf16 exact
__device__ float g_wsm[H_DIM * K_DIM];                            // softmaxed conv kernels

// ---------------- helpers ----------------
static __device__ __forceinline__ uint32_t smem_u32(const void* p) {
    uint32_t a;
    asm("{ .reg .u64 t; cvta.to.shared.u64 t, %1; cvt.u32.u64 %0, t; }" : "=r"(a) : "l"(p));
    return a;
}
static __device__ __forceinline__ uint32_t pack2(float a, float b) {
    __nv_bfloat162 h = __floats2bfloat162_rn(a, b);
    return *reinterpret_cast<uint32_t*>(&h);
}

#define CP_ASYNC16(dst, src) \
    asm volatile("cp.async.cg.shared.global [%0], [%1], 16;" :: "r"(dst), "l"(src) : "memory")
#define CP_COMMIT() asm volatile("cp.async.commit_group;" ::: "memory")
#define CP_WAIT1()  asm volatile("cp.async.wait_group 1;" ::: "memory")

#define LDSM_X4(r0, r1, r2, r3, a) \
    asm volatile("ldmatrix.sync.aligned.m8n8.x4.shared.b16 {%0,%1,%2,%3}, [%4];" \
        : "=r"(r0), "=r"(r1), "=r"(r2), "=r"(r3) : "r"(a))

#define MMA_BF16(d, a, b0, b1) \
    asm volatile("mma.sync.aligned.m16n8k16.row.col.f32.bf16.bf16.f32 " \
        "{%0,%1,%2,%3}, {%4,%5,%6,%7}, {%8,%9}, {%0,%1,%2,%3};" \
        : "+f"((d)[0]), "+f"((d)[1]), "+f"((d)[2]), "+f"((d)[3]) \
        : "r"((a)[0]), "r"((a)[1]), "r"((a)[2]), "r"((a)[3]), "r"(b0), "r"(b1))

// ---------------- prep: quantize W -> bf16 (exact) + softmax ----------------
__global__ void prep_kernel(const float* __restrict__ W,
                            const float* __restrict__ conv_w) {
    int i = blockIdx.x * 256 + threadIdx.x;
    if (i < C_DIM * C_DIM) {
        float w = W[i];
        float a = fabsf(w) + 1e-12f;
        float e = rintf(log2f(a));
        float q = copysignf(exp2f(e), w);
        g_wqb[i] = __float2bfloat16((w == 0.0f) ? 0.0f : q);
    }
    if (blockIdx.x == 0 && threadIdx.x < H_DIM) {
        int h = threadIdx.x;
        float v[K_DIM];
        float m = -1e30f;
        #pragma unroll
        for (int k = 0; k < K_DIM; ++k) { v[k] = conv_w[h * K_DIM + k]; m = fmaxf(m, v[k]); }
        float s = 0.0f;
        #pragma unroll
        for (int k = 0; k < K_DIM; ++k) { v[k] = expf(v[k] - m); s += v[k]; }
        float inv = 1.0f / s;
        #pragma unroll
        for (int k = 0; k < K_DIM; ++k) g_wsm[h * K_DIM + k] = v[k] * inv;
    }
}

// ---------------- convert x -> hi/lo bf16 ----------------
__global__ void __launch_bounds__(256) convert_x(const float* __restrict__ x) {
    size_t i = (size_t)blockIdx.x * 256 + threadIdx.x;   // one float4 per thread
    float4 v = ((const float4*)x)[i];
    float hx = __bfloat162float(__float2bfloat16(v.x));
    float hy = __bfloat162float(__float2bfloat16(v.y));
    float hz = __bfloat162float(__float2bfloat16(v.z));
    float hw = __bfloat162float(__float2bfloat16(v.w));
    ((uint2*)g_xhi)[i] = make_uint2(pack2(v.x, v.y), pack2(v.z, v.w));
    ((uint2*)g_xlo)[i] = make_uint2(pack2(v.x - hx, v.y - hy), pack2(v.z - hz, v.w - hw));
}

// ---------------- GEMM via mma.sync bf16 ----------------
// y[m,n] = sum_c (xhi+xlo)[m,c] * Wq[n,c] + b[n]
// CTA tile 128x256, BK=64, 16 warps (4x4), warp tile 32x64, 3-stage cp.async.
#define BM 128
#define BN 256
#define BK 64
#define ST_AHI 0
#define ST_ALO 16384
#define ST_B   32768
#define ST_SIZE 65536
#define SMEM_GEMM (3 * ST_SIZE)
#define KCH (C_DIM / BK)   // 8

__global__ void __launch_bounds__(512, 1) gemm_mma(const float* __restrict__ bias) {
    extern __shared__ char sm[];
    const uint32_t sb = smem_u32(sm);
    const int tid = threadIdx.x;
    const int lane = tid & 31;
    const int wid = tid >> 5;
    const int wm = wid & 3;          // warp row 0..3
    const int wn = wid >> 2;         // warp col 0..3
    const int m0 = blockIdx.y * BM;
    const int n0 = blockIdx.x * BN;

    float acc[2][8][4];
    #pragma unroll
    for (int i = 0; i < 2; ++i)
        #pragma unroll
        for (int j = 0; j < 8; ++j)
            #pragma unroll
            for (int q = 0; q < 4; ++q) acc[i][j][q] = 0.0f;

    // ---- async load mapping ----
    // A (hi & lo): 128 rows x 8 chunks(16B) -> 1024 ops, 2/thread each
    // B: 256 rows x 8 chunks -> 2048 ops, 4/thread
    const int ar0 = (tid + 0)   >> 3, ac0 = (tid + 0)   & 7;
    const int ar1 = (tid + 512) >> 3, ac1 = (tid + 512) & 7;

    auto issue_stage = [&](int stage, int kc) {
        const uint32_t base = sb + stage * ST_SIZE;
        const int kt = kc * BK;
        {   // A hi/lo
            const __nv_bfloat16* s0h = g_xhi + (size_t)(m0 + ar0) * C_DIM + kt + ac0 * 8;
            const __nv_bfloat16* s1h = g_xhi + (size_t)(m0 + ar1) * C_DIM + kt + ac1 * 8;
            const __nv_bfloat16* s0l = g_xlo + (size_t)(m0 + ar0) * C_DIM + kt + ac0 * 8;
            const __nv_bfloat16* s1l = g_xlo + (size_t)(m0 + ar1) * C_DIM + kt + ac1 * 8;
            uint32_t d0 = base + ST_AHI + ar0 * 128 + ((ac0 ^ (ar0 & 7)) * 16);
            uint32_t d1 = base + ST_AHI + ar1 * 128 + ((ac1 ^ (ar1 & 7)) * 16);
            CP_ASYNC16(d0, s0h);
            CP_ASYNC16(d1, s1h);
            CP_ASYNC16(d0 + (ST_ALO - ST_AHI), s0l);
            CP_ASYNC16(d1 + (ST_ALO - ST_AHI), s1l);
        }
        #pragma unroll
        for (int j = 0; j < 4; ++j) {
            int idx = tid + j * 512;
            int r = idx >> 3, c = idx & 7;
            const __nv_bfloat16* s = g_wqb + (size_t)(n0 + r) * C_DIM + kt + c * 8;
            uint32_t d = base + ST_B + r * 128 + ((c ^ (r & 7)) * 16);
            CP_ASYNC16(d, s);
        }
    };

    issue_stage(0, 0); CP_COMMIT();
    issue_stage(1, 1); CP_COMMIT();

    // ---- ldmatrix per-lane geometry ----
    const int arow  = wm * 32 + (lane & 15);   // A row for this lane (mt adds 16)
    const int axor  = arow & 7;
    const int ahalf = lane >> 4;               // k-half selector
    const int bmidx = lane >> 3;               // 0..3
    const int brow0 = wn * 64 + ((bmidx >> 1) << 3) + (lane & 7);
    const int bxor  = lane & 7;
    const int bko   = bmidx & 1;

    #pragma unroll 1
    for (int i = 0; i < KCH; ++i) {
        CP_WAIT1();
        __syncthreads();
        if (i + 2 < KCH) issue_stage((i + 2) % 3, i + 2);
        CP_COMMIT();

        const uint32_t base = sb + (i % 3) * ST_SIZE;
        const uint32_t ahi_b = base + ST_AHI + arow * 128;
        const uint32_t alo_b = base + ST_ALO + arow * 128;
        const uint32_t b_b   = base + ST_B + brow0 * 128;

        #pragma unroll
        for (int ks = 0; ks < 4; ++ks) {
            uint32_t coff = (((ks * 2 + ahalf) ^ axor) * 16);
            uint32_t ah[2][4], al[2][4], bb[4][4];
            #pragma unroll
            for (int mt = 0; mt < 2; ++mt) {
                LDSM_X4(ah[mt][0], ah[mt][1], ah[mt][2], ah[mt][3], ahi_b + mt * 2048 + coff);
                LDSM_X4(al[mt][0], al[mt][1], al[mt][2], al[mt][3], alo_b + mt * 2048 + coff);
            }
            uint32_t bcoff = (((ks * 2 + bko) ^ bxor) * 16);
            #pragma unroll
            for (int np = 0; np < 4; ++np) {
                LDSM_X4(bb[np][0], bb[np][1], bb[np][2], bb[np][3], b_b + np * 2048 + bcoff);
            }
            #pragma unroll
            for (int mt = 0; mt < 2; ++mt) {
                #pragma unroll
                for (int nt = 0; nt < 8; ++nt) {
                    uint32_t b0 = bb[nt >> 1][(nt & 1) * 2];
                    uint32_t b1 = bb[nt >> 1][(nt & 1) * 2 + 1];
                    MMA_BF16(acc[mt][nt], ah[mt], b0, b1);
                    MMA_BF16(acc[mt][nt], al[mt], b0, b1);
                }
            }
        }
    }

    // ---- epilogue: bias + store ----
    const int r0 = lane >> 2;
    const int c2 = (lane & 3) * 2;
    #pragma unroll
    for (int mt = 0; mt < 2; ++mt) {
        int row = m0 + wm * 32 + mt * 16 + r0;
        #pragma unroll
        for (int nt = 0; nt < 8; ++nt) {
            int col = n0 + wn * 64 + nt * 8 + c2;
            float bx = __ldg(&bias[col]);
            float by = __ldg(&bias[col + 1]);
            float2 v0 = make_float2(acc[mt][nt][0] + bx, acc[mt][nt][1] + by);
            float2 v1 = make_float2(acc[mt][nt][2] + bx, acc[mt][nt][3] + by);
            *(float2*)&g_y[(size_t)row * C_DIM + col] = v0;
            *(float2*)&g_y[(size_t)(row + 8) * C_DIM + col] = v1;
        }
    }
}

// ---------------- depthwise conv along time ----------------
#define TC_TILE 64

__global__ void __launch_bounds__(512) conv_kernel(float* __restrict__ out) {
    const int c  = threadIdx.x;
    const int b  = blockIdx.y;
    const int t0 = blockIdx.x * TC_TILE;
    const int h  = c >> 6;

    float w[K_DIM];
    #pragma unroll
    for (int k = 0; k < K_DIM; ++k) w[k] = g_wsm[h * K_DIM + k];

    float win[K_DIM];
    #pragma unroll
    for (int j = 0; j < K_DIM - 1; ++j) {
        int tt = t0 - PAD_L + j;
        win[j] = (tt >= 0 && tt < T_DIM)
                   ? g_y[((size_t)tt * B_DIM + b) * C_DIM + c] : 0.0f;
    }

    for (int t = t0; t < t0 + TC_TILE; ++t) {
        int tt = t + (K_DIM - 1 - PAD_L);
        win[K_DIM - 1] = (tt < T_DIM)
                   ? g_y[((size_t)tt * B_DIM + b) * C_DIM + c] : 0.0f;
        float a = 0.0f;
        #pragma unroll
        for (int j = 0; j < K_DIM; ++j) a = fmaf(w[j], win[j], a);
        out[((size_t)t * B_DIM + b) * C_DIM + c] = a;
        #pragma unroll
        for (int j = 0; j < K_DIM - 1; ++j) win[j] = win[j + 1];
    }
}

// ---------------- launch ----------------
extern "C" void kernel_launch(void* const* d_in, const int* in_sizes, int n_in,
                              void* d_out, int out_size) {
    const float* x       = (const float*)d_in[0];
    const float* shift_W = (const float*)d_in[1];
    const float* shift_b = (const float*)d_in[2];
    const float* weight  = (const float*)d_in[3];
    float* out = (float*)d_out;

    cudaFuncSetAttribute(gemm_mma, cudaFuncAttributeMaxDynamicSharedMemorySize, SMEM_GEMM);

    prep_kernel<<<(C_DIM * C_DIM + 255) / 256, 256>>>(shift_W, weight);
    convert_x<<<(M_DIM * C_DIM / 4) / 256, 256>>>(x);

    dim3 ggrid(C_DIM / BN, M_DIM / BM);   // (2, 512)
    gemm_mma<<<ggrid, 512, SMEM_GEMM>>>(shift_b);

    dim3 cgrid(T_DIM / TC_TILE, B_DIM);
    conv_kernel<<<cgrid, 512>>>(out);
}

// round 4
// speedup vs baseline: 4.3814x; 1.5471x over previous
#include <cuda_runtime.h>
#include <cuda_fp16.h>
#include <math.h>
#include <stdint.h>

#define T_DIM 4096
#define B_DIM 16
#define C_DIM 512
#define M_DIM (T_DIM * B_DIM)      // 65536
#define H_DIM 8
#define K_DIM 7
#define PAD_L 3

// ---------------- scratch (no allocations allowed) ----------------
__device__ __align__(16) float g_y[(size_t)M_DIM * C_DIM];     // GEMM out, 128 MB
__device__ __align__(16) __half g_xh[(size_t)M_DIM * C_DIM];   // x in fp16, 64 MB
__device__ __align__(16) __half g_wqh[C_DIM * C_DIM];          // quantized W, fp16 exact
__device__ float g_wsm[H_DIM * K_DIM];                         // softmaxed conv kernels

// ---------------- helpers ----------------
static __device__ __forceinline__ uint32_t smem_u32(const void* p) {
    uint32_t a;
    asm("{ .reg .u64 t; cvta.to.shared.u64 t, %1; cvt.u32.u64 %0, t; }" : "=r"(a) : "l"(p));
    return a;
}

#define CP_ASYNC16(dst, src) \
    asm volatile("cp.async.cg.shared.global [%0], [%1], 16;" :: "r"(dst), "l"(src) : "memory")
#define CP_COMMIT() asm volatile("cp.async.commit_group;" ::: "memory")
#define CP_WAIT1()  asm volatile("cp.async.wait_group 1;" ::: "memory")

#define LDSM_X4(r0, r1, r2, r3, a) \
    asm volatile("ldmatrix.sync.aligned.m8n8.x4.shared.b16 {%0,%1,%2,%3}, [%4];" \
        : "=r"(r0), "=r"(r1), "=r"(r2), "=r"(r3) : "r"(a))

#define MMA_F16(d, a, b0, b1) \
    asm volatile("mma.sync.aligned.m16n8k16.row.col.f32.f16.f16.f32 " \
        "{%0,%1,%2,%3}, {%4,%5,%6,%7}, {%8,%9}, {%0,%1,%2,%3};" \
        : "+f"((d)[0]), "+f"((d)[1]), "+f"((d)[2]), "+f"((d)[3]) \
        : "r"((a)[0]), "r"((a)[1]), "r"((a)[2]), "r"((a)[3]), "r"(b0), "r"(b1))

// ---------------- prep: quantize W -> fp16 (exact powers of 2) + softmax ----------------
__global__ void prep_kernel(const float* __restrict__ W,
                            const float* __restrict__ conv_w) {
    int i = blockIdx.x * 256 + threadIdx.x;
    if (i < C_DIM * C_DIM) {
        float w = W[i];
        float a = fabsf(w) + 1e-12f;
        float e = rintf(log2f(a));
        float q = copysignf(exp2f(e), w);
        g_wqh[i] = __float2half((w == 0.0f) ? 0.0f : q);
    }
    if (blockIdx.x == 0 && threadIdx.x < H_DIM) {
        int h = threadIdx.x;
        float v[K_DIM];
        float m = -1e30f;
        #pragma unroll
        for (int k = 0; k < K_DIM; ++k) { v[k] = conv_w[h * K_DIM + k]; m = fmaxf(m, v[k]); }
        float s = 0.0f;
        #pragma unroll
        for (int k = 0; k < K_DIM; ++k) { v[k] = expf(v[k] - m); s += v[k]; }
        float inv = 1.0f / s;
        #pragma unroll
        for (int k = 0; k < K_DIM; ++k) g_wsm[h * K_DIM + k] = v[k] * inv;
    }
}

// ---------------- convert x -> fp16 ----------------
__global__ void __launch_bounds__(256) convert_x(const float* __restrict__ x) {
    size_t i = (size_t)blockIdx.x * 256 + threadIdx.x;   // one float4 per thread
    float4 v = ((const float4*)x)[i];
    __half2 a = __floats2half2_rn(v.x, v.y);
    __half2 b = __floats2half2_rn(v.z, v.w);
    ((uint2*)g_xh)[i] = make_uint2(*(uint32_t*)&a, *(uint32_t*)&b);
}

// ---------------- GEMM via mma.sync fp16 ----------------
// y[m,n] = sum_c x[m,c] * Wq[n,c] + b[n]
// CTA tile 128x256, BK=64, 16 warps (4x4), warp tile 32x64, 3-stage cp.async.
#define BM 128
#define BN 256
#define BK 64
#define ST_A 0
#define ST_B 16384
#define ST_SIZE 49152
#define SMEM_GEMM (3 * ST_SIZE)
#define KCH (C_DIM / BK)   // 8

__global__ void __launch_bounds__(512, 1) gemm_mma(const float* __restrict__ bias) {
    extern __shared__ char sm[];
    const uint32_t sb = smem_u32(sm);
    const int tid = threadIdx.x;
    const int lane = tid & 31;
    const int wid = tid >> 5;
    const int wm = wid & 3;          // warp row 0..3
    const int wn = wid >> 2;         // warp col 0..3
    const int m0 = blockIdx.y * BM;
    const int n0 = blockIdx.x * BN;

    float acc[2][8][4];
    #pragma unroll
    for (int i = 0; i < 2; ++i)
        #pragma unroll
        for (int j = 0; j < 8; ++j)
            #pragma unroll
            for (int q = 0; q < 4; ++q) acc[i][j][q] = 0.0f;

    // A: 128 rows x 8 chunks(16B) = 1024 ops, 2/thread. B: 256 x 8 = 2048, 4/thread.
    const int ar0 = (tid + 0)   >> 3, ac0 = (tid + 0)   & 7;
    const int ar1 = (tid + 512) >> 3, ac1 = (tid + 512) & 7;

    auto issue_stage = [&](int stage, int kc) {
        const uint32_t base = sb + stage * ST_SIZE;
        const int kt = kc * BK;
        {
            const __half* s0 = g_xh + (size_t)(m0 + ar0) * C_DIM + kt + ac0 * 8;
            const __half* s1 = g_xh + (size_t)(m0 + ar1) * C_DIM + kt + ac1 * 8;
            uint32_t d0 = base + ST_A + ar0 * 128 + ((ac0 ^ (ar0 & 7)) * 16);
            uint32_t d1 = base + ST_A + ar1 * 128 + ((ac1 ^ (ar1 & 7)) * 16);
            CP_ASYNC16(d0, s0);
            CP_ASYNC16(d1, s1);
        }
        #pragma unroll
        for (int j = 0; j < 4; ++j) {
            int idx = tid + j * 512;
            int r = idx >> 3, c = idx & 7;
            const __half* s = g_wqh + (size_t)(n0 + r) * C_DIM + kt + c * 8;
            uint32_t d = base + ST_B + r * 128 + ((c ^ (r & 7)) * 16);
            CP_ASYNC16(d, s);
        }
    };

    issue_stage(0, 0); CP_COMMIT();
    issue_stage(1, 1); CP_COMMIT();

    // ldmatrix per-lane geometry
    const int arow  = wm * 32 + (lane & 15);
    const int axor  = arow & 7;
    const int ahalf = lane >> 4;
    const int bmidx = lane >> 3;
    const int brow0 = wn * 64 + ((bmidx >> 1) << 3) + (lane & 7);
    const int bxor  = lane & 7;
    const int bko   = bmidx & 1;

    #pragma unroll 1
    for (int i = 0; i < KCH; ++i) {
        CP_WAIT1();
        __syncthreads();
        if (i + 2 < KCH) issue_stage((i + 2) % 3, i + 2);
        CP_COMMIT();

        const uint32_t base = sb + (i % 3) * ST_SIZE;
        const uint32_t a_b = base + ST_A + arow * 128;
        const uint32_t b_b = base + ST_B + brow0 * 128;

        #pragma unroll
        for (int ks = 0; ks < 4; ++ks) {
            uint32_t coff = (((ks * 2 + ahalf) ^ axor) * 16);
            uint32_t ah[2][4], bb[4][4];
            #pragma unroll
            for (int mt = 0; mt < 2; ++mt)
                LDSM_X4(ah[mt][0], ah[mt][1], ah[mt][2], ah[mt][3], a_b + mt * 2048 + coff);
            uint32_t bcoff = (((ks * 2 + bko) ^ bxor) * 16);
            #pragma unroll
            for (int np = 0; np < 4; ++np)
                LDSM_X4(bb[np][0], bb[np][1], bb[np][2], bb[np][3], b_b + np * 2048 + bcoff);
            #pragma unroll
            for (int mt = 0; mt < 2; ++mt)
                #pragma unroll
                for (int nt = 0; nt < 8; ++nt) {
                    uint32_t b0 = bb[nt >> 1][(nt & 1) * 2];
                    uint32_t b1 = bb[nt >> 1][(nt & 1) * 2 + 1];
                    MMA_F16(acc[mt][nt], ah[mt], b0, b1);
                }
        }
    }

    // epilogue: bias + store
    const int r0 = lane >> 2;
    const int c2 = (lane & 3) * 2;
    #pragma unroll
    for (int mt = 0; mt < 2; ++mt) {
        int row = m0 + wm * 32 + mt * 16 + r0;
        #pragma unroll
        for (int nt = 0; nt < 8; ++nt) {
            int col = n0 + wn * 64 + nt * 8 + c2;
            float bx = __ldg(&bias[col]);
            float by = __ldg(&bias[col + 1]);
            float2 v0 = make_float2(acc[mt][nt][0] + bx, acc[mt][nt][1] + by);
            float2 v1 = make_float2(acc[mt][nt][2] + bx, acc[mt][nt][3] + by);
            *(float2*)&g_y[(size_t)row * C_DIM + col] = v0;
            *(float2*)&g_y[(size_t)(row + 8) * C_DIM + col] = v1;
        }
    }
}

// ---------------- depthwise conv along time (float4, 8-deep pipelined) ----------------
#define TCONV 32

static __device__ __forceinline__ void fma4(float4& o, float w, const float4& c) {
    o.x = fmaf(w, c.x, o.x); o.y = fmaf(w, c.y, o.y);
    o.z = fmaf(w, c.z, o.z); o.w = fmaf(w, c.w, o.w);
}

__global__ void __launch_bounds__(128) conv_kernel(float* __restrict__ out) {
    const int q  = threadIdx.x;            // channel group: 4 channels q*4..q*4+3
    const int b  = blockIdx.y;
    const int t0 = blockIdx.x * TCONV;
    const int h  = q >> 4;                 // (q*4)/64

    float w[K_DIM];
    #pragma unroll
    for (int k = 0; k < K_DIM; ++k) w[k] = g_wsm[h * K_DIM + k];

    const float4* Y = (const float4*)g_y;    // index: (t*16+b)*128 + q
    float4* O = (float4*)out;
    const float4 z4 = make_float4(0.f, 0.f, 0.f, 0.f);

    float4 carry[6];
    #pragma unroll
    for (int j = 0; j < 6; ++j) {
        int tt = t0 - PAD_L + j;
        carry[j] = (tt >= 0) ? Y[(size_t)(tt * B_DIM + b) * 128 + q] : z4;
    }

    #pragma unroll
    for (int ch = 0; ch < TCONV / 8; ++ch) {
        const int tb = t0 + ch * 8;
        float4 cmb[14];
        #pragma unroll
        for (int j = 0; j < 6; ++j) cmb[j] = carry[j];
        #pragma unroll
        for (int j = 0; j < 8; ++j) {
            int tt = tb + PAD_L + j;
            cmb[6 + j] = (tt < T_DIM) ? Y[(size_t)(tt * B_DIM + b) * 128 + q] : z4;
        }
        #pragma unroll
        for (int i = 0; i < 8; ++i) {
            float4 o = z4;
            #pragma unroll
            for (int k = 0; k < K_DIM; ++k) fma4(o, w[k], cmb[i + k]);
            O[(size_t)((tb + i) * B_DIM + b) * 128 + q] = o;
        }
        #pragma unroll
        for (int j = 0; j < 6; ++j) carry[j] = cmb[8 + j];
    }
}

// ---------------- launch ----------------
extern "C" void kernel_launch(void* const* d_in, const int* in_sizes, int n_in,
                              void* d_out, int out_size) {
    const float* x       = (const float*)d_in[0];
    const float* shift_W = (const float*)d_in[1];
    const float* shift_b = (const float*)d_in[2];
    const float* weight  = (const float*)d_in[3];
    float* out = (float*)d_out;

    cudaFuncSetAttribute(gemm_mma, cudaFuncAttributeMaxDynamicSharedMemorySize, SMEM_GEMM);

    prep_kernel<<<(C_DIM * C_DIM + 255) / 256, 256>>>(shift_W, weight);
    convert_x<<<(M_DIM * C_DIM / 4) / 256, 256>>>(x);

    dim3 ggrid(C_DIM / BN, M_DIM / BM);   // (2, 512)
    gemm_mma<<<ggrid, 512, SMEM_GEMM>>>(shift_b);

    dim3 cgrid(T_DIM / TCONV, B_DIM);     // (128, 16)
    conv_kernel<<<cgrid, 128>>>(out);
}

// round 5
// speedup vs baseline: 4.8229x; 1.1008x over previous
#include <cuda_runtime.h>
#include <cuda_fp16.h>
#include <math.h>
#include <stdint.h>

#define T_DIM 4096
#define B_DIM 16
#define C_DIM 512
#define M_DIM (T_DIM * B_DIM)      // 65536
#define H_DIM 8
#define K_DIM 7
#define PAD_L 3

// ---------------- scratch (no allocations allowed) ----------------
__device__ __align__(16) float g_y[(size_t)M_DIM * C_DIM];     // GEMM out, 128 MB
__device__ __align__(16) __half g_wqh[C_DIM * C_DIM];          // quantized W, fp16 exact
__device__ float g_wsm[H_DIM * K_DIM];                         // softmaxed conv kernels

// ---------------- helpers ----------------
static __device__ __forceinline__ uint32_t smem_u32(const void* p) {
    uint32_t a;
    asm("{ .reg .u64 t; cvta.to.shared.u64 t, %1; cvt.u32.u64 %0, t; }" : "=r"(a) : "l"(p));
    return a;
}

#define CP_ASYNC16(dst, src) \
    asm volatile("cp.async.cg.shared.global [%0], [%1], 16;" :: "r"(dst), "l"(src) : "memory")
#define CP_COMMIT() asm volatile("cp.async.commit_group;" ::: "memory")
#define CP_WAIT1()  asm volatile("cp.async.wait_group 1;" ::: "memory")

#define LDSM_X4(r0, r1, r2, r3, a) \
    asm volatile("ldmatrix.sync.aligned.m8n8.x4.shared.b16 {%0,%1,%2,%3}, [%4];" \
        : "=r"(r0), "=r"(r1), "=r"(r2), "=r"(r3) : "r"(a))

#define MMA_F16(d, a, b0, b1) \
    asm volatile("mma.sync.aligned.m16n8k16.row.col.f32.f16.f16.f32 " \
        "{%0,%1,%2,%3}, {%4,%5,%6,%7}, {%8,%9}, {%0,%1,%2,%3};" \
        : "+f"((d)[0]), "+f"((d)[1]), "+f"((d)[2]), "+f"((d)[3]) \
        : "r"((a)[0]), "r"((a)[1]), "r"((a)[2]), "r"((a)[3]), "r"(b0), "r"(b1))

static __device__ __forceinline__ uint32_t packh2(float a, float b) {
    __half2 h = __floats2half2_rn(a, b);
    return *reinterpret_cast<uint32_t*>(&h);
}

// ---------------- prep: quantize W -> fp16 (exact powers of 2) + softmax ----------------
__global__ void prep_kernel(const float* __restrict__ W,
                            const float* __restrict__ conv_w) {
    int i = blockIdx.x * 256 + threadIdx.x;
    if (i < C_DIM * C_DIM) {
        float w = W[i];
        float a = fabsf(w) + 1e-12f;
        float e = rintf(log2f(a));
        float q = copysignf(exp2f(e), w);
        g_wqh[i] = __float2half((w == 0.0f) ? 0.0f : q);
    }
    if (blockIdx.x == 0 && threadIdx.x < H_DIM) {
        int h = threadIdx.x;
        float v[K_DIM];
        float m = -1e30f;
        #pragma unroll
        for (int k = 0; k < K_DIM; ++k) { v[k] = conv_w[h * K_DIM + k]; m = fmaxf(m, v[k]); }
        float s = 0.0f;
        #pragma unroll
        for (int k = 0; k < K_DIM; ++k) { v[k] = expf(v[k] - m); s += v[k]; }
        float inv = 1.0f / s;
        #pragma unroll
        for (int k = 0; k < K_DIM; ++k) g_wsm[h * K_DIM + k] = v[k] * inv;
    }
}

// ---------------- GEMM via mma.sync fp16, fused fp32->fp16 A conversion ----------------
// y[m,n] = sum_c x[m,c] * Wq[n,c] + b[n]
// CTA tile 128x256, BK=64, 16 warps (4x4), warp tile 32x64.
// B: 3-stage cp.async.  A: LDG fp32 -> cvt -> STS, prefetched across the barrier.
#define BM 128
#define BN 256
#define BK 64
#define ST_A 0
#define ST_B 16384
#define ST_SIZE 49152
#define SMEM_GEMM (3 * ST_SIZE)
#define KCH (C_DIM / BK)   // 8

__global__ void __launch_bounds__(512, 1) gemm_mma(const float* __restrict__ x,
                                                   const float* __restrict__ bias) {
    extern __shared__ char sm[];
    const uint32_t sb = smem_u32(sm);
    const int tid = threadIdx.x;
    const int lane = tid & 31;
    const int wid = tid >> 5;
    const int wm = wid & 3;          // warp row 0..3
    const int wn = wid >> 2;         // warp col 0..3
    const int m0 = blockIdx.y * BM;
    const int n0 = blockIdx.x * BN;

    float acc[2][8][4];
    #pragma unroll
    for (int i = 0; i < 2; ++i)
        #pragma unroll
        for (int j = 0; j < 8; ++j)
            #pragma unroll
            for (int q = 0; q < 4; ++q) acc[i][j][q] = 0.0f;

    // A: 128 rows x 16 float4 per stage = 2048 ops, 4/thread (LDG path)
    int ar[4], ag[4];
    #pragma unroll
    for (int t = 0; t < 4; ++t) { int idx = tid + t * 512; ar[t] = idx >> 4; ag[t] = idx & 15; }

    auto ldgA = [&](int kc, float4* regs) {
        const int kt = kc * BK;
        #pragma unroll
        for (int t = 0; t < 4; ++t)
            regs[t] = *(const float4*)&x[(size_t)(m0 + ar[t]) * C_DIM + kt + ag[t] * 4];
    };
    auto stsA = [&](int stage, const float4* regs) {
        const uint32_t base = sb + stage * ST_SIZE + ST_A;
        #pragma unroll
        for (int t = 0; t < 4; ++t) {
            uint32_t d = base + ar[t] * 128 + (((ag[t] >> 1) ^ (ar[t] & 7)) * 16) + (ag[t] & 1) * 8;
            *(uint2*)(size_t)0; // placeholder removed below
        }
    };
    (void)0;

    auto issueB = [&](int stage, int kc) {
        const uint32_t base = sb + stage * ST_SIZE;
        const int kt = kc * BK;
        #pragma unroll
        for (int j = 0; j < 4; ++j) {
            int idx = tid + j * 512;
            int r = idx >> 3, c = idx & 7;
            const __half* s = g_wqh + (size_t)(n0 + r) * C_DIM + kt + c * 8;
            uint32_t d = base + ST_B + r * 128 + ((c ^ (r & 7)) * 16);
            CP_ASYNC16(d, s);
        }
    };

    // manual STS of converted A (lambda above unused; do inline for correctness)
    auto storeA = [&](int stage, const float4* regs) {
        const uint32_t base = sb + stage * ST_SIZE + ST_A;
        #pragma unroll
        for (int t = 0; t < 4; ++t) {
            uint32_t d = base + ar[t] * 128 + (((ag[t] >> 1) ^ (ar[t] & 7)) * 16) + (ag[t] & 1) * 8;
            uint2 v = make_uint2(packh2(regs[t].x, regs[t].y), packh2(regs[t].z, regs[t].w));
            asm volatile("st.shared.v2.b32 [%0], {%1, %2};" :: "r"(d), "r"(v.x), "r"(v.y) : "memory");
        }
    };

    // prologue: stages 0 and 1
    float4 areg[4];
    ldgA(0, areg); storeA(0, areg);
    issueB(0, 0); CP_COMMIT();
    ldgA(1, areg); storeA(1, areg);
    issueB(1, 1); CP_COMMIT();

    // ldmatrix per-lane geometry
    const int arow  = wm * 32 + (lane & 15);
    const int axor  = arow & 7;
    const int ahalf = lane >> 4;
    const int bmidx = lane >> 3;
    const int brow0 = wn * 64 + ((bmidx >> 1) << 3) + (lane & 7);
    const int bxor  = lane & 7;
    const int bko   = bmidx & 1;

    #pragma unroll 1
    for (int i = 0; i < KCH; ++i) {
        const bool pf = (i + 2 < KCH);
        if (pf) ldgA(i + 2, areg);      // LDG before the barrier: latency hidden
        CP_WAIT1();
        __syncthreads();
        if (pf) {
            storeA((i + 2) % 3, areg);  // STS after barrier: buffer free
            issueB((i + 2) % 3, i + 2);
        }
        CP_COMMIT();

        const uint32_t base = sb + (i % 3) * ST_SIZE;
        const uint32_t a_b = base + ST_A + arow * 128;
        const uint32_t b_b = base + ST_B + brow0 * 128;

        #pragma unroll
        for (int ks = 0; ks < 4; ++ks) {
            uint32_t coff = (((ks * 2 + ahalf) ^ axor) * 16);
            uint32_t ah[2][4], bb[4][4];
            #pragma unroll
            for (int mt = 0; mt < 2; ++mt)
                LDSM_X4(ah[mt][0], ah[mt][1], ah[mt][2], ah[mt][3], a_b + mt * 2048 + coff);
            uint32_t bcoff = (((ks * 2 + bko) ^ bxor) * 16);
            #pragma unroll
            for (int np = 0; np < 4; ++np)
                LDSM_X4(bb[np][0], bb[np][1], bb[np][2], bb[np][3], b_b + np * 2048 + bcoff);
            #pragma unroll
            for (int mt = 0; mt < 2; ++mt)
                #pragma unroll
                for (int nt = 0; nt < 8; ++nt) {
                    uint32_t b0 = bb[nt >> 1][(nt & 1) * 2];
                    uint32_t b1 = bb[nt >> 1][(nt & 1) * 2 + 1];
                    MMA_F16(acc[mt][nt], ah[mt], b0, b1);
                }
        }
    }

    // epilogue: bias + store
    const int r0 = lane >> 2;
    const int c2 = (lane & 3) * 2;
    #pragma unroll
    for (int mt = 0; mt < 2; ++mt) {
        int row = m0 + wm * 32 + mt * 16 + r0;
        #pragma unroll
        for (int nt = 0; nt < 8; ++nt) {
            int col = n0 + wn * 64 + nt * 8 + c2;
            float bx = __ldg(&bias[col]);
            float by = __ldg(&bias[col + 1]);
            float2 v0 = make_float2(acc[mt][nt][0] + bx, acc[mt][nt][1] + by);
            float2 v1 = make_float2(acc[mt][nt][2] + bx, acc[mt][nt][3] + by);
            *(float2*)&g_y[(size_t)row * C_DIM + col] = v0;
            *(float2*)&g_y[(size_t)(row + 8) * C_DIM + col] = v1;
        }
    }
}

// ---------------- depthwise conv along time (float4, 4-deep pipelined) ----------------
#define TCONV 32

static __device__ __forceinline__ void fma4(float4& o, float w, const float4& c) {
    o.x = fmaf(w, c.x, o.x); o.y = fmaf(w, c.y, o.y);
    o.z = fmaf(w, c.z, o.z); o.w = fmaf(w, c.w, o.w);
}

__global__ void __launch_bounds__(128) conv_kernel(float* __restrict__ out) {
    const int q  = threadIdx.x;            // channel group: 4 channels q*4..q*4+3
    const int b  = blockIdx.y;
    const int t0 = blockIdx.x * TCONV;
    const int h  = q >> 4;                 // (q*4)/64

    float w[K_DIM];
    #pragma unroll
    for (int k = 0; k < K_DIM; ++k) w[k] = g_wsm[h * K_DIM + k];

    const float4* Y = (const float4*)g_y;    // index: (t*16+b)*128 + q
    float4* O = (float4*)out;
    const float4 z4 = make_float4(0.f, 0.f, 0.f, 0.f);

    float4 carry[6];
    #pragma unroll
    for (int j = 0; j < 6; ++j) {
        int tt = t0 - PAD_L + j;
        carry[j] = (tt >= 0) ? Y[(size_t)(tt * B_DIM + b) * 128 + q] : z4;
    }

    #pragma unroll
    for (int ch = 0; ch < TCONV / 4; ++ch) {
        const int tb = t0 + ch * 4;
        float4 cmb[10];
        #pragma unroll
        for (int j = 0; j < 6; ++j) cmb[j] = carry[j];
        #pragma unroll
        for (int j = 0; j < 4; ++j) {
            int tt = tb + PAD_L + j;
            cmb[6 + j] = (tt < T_DIM) ? Y[(size_t)(tt * B_DIM + b) * 128 + q] : z4;
        }
        #pragma unroll
        for (int i = 0; i < 4; ++i) {
            float4 o = z4;
            #pragma unroll
            for (int k = 0; k < K_DIM; ++k) fma4(o, w[k], cmb[i + k]);
            O[(size_t)((tb + i) * B_DIM + b) * 128 + q] = o;
        }
        #pragma unroll
        for (int j = 0; j < 6; ++j) carry[j] = cmb[4 + j];
    }
}

// ---------------- launch ----------------
extern "C" void kernel_launch(void* const* d_in, const int* in_sizes, int n_in,
                              void* d_out, int out_size) {
    const float* x       = (const float*)d_in[0];
    const float* shift_W = (const float*)d_in[1];
    const float* shift_b = (const float*)d_in[2];
    const float* weight  = (const float*)d_in[3];
    float* out = (float*)d_out;

    cudaFuncSetAttribute(gemm_mma, cudaFuncAttributeMaxDynamicSharedMemorySize, SMEM_GEMM);

    prep_kernel<<<(C_DIM * C_DIM + 255) / 256, 256>>>(shift_W, weight);

    dim3 ggrid(C_DIM / BN, M_DIM / BM);   // (2, 512)
    gemm_mma<<<ggrid, 512, SMEM_GEMM>>>(x, shift_b);

    dim3 cgrid(T_DIM / TCONV, B_DIM);     // (128, 16)
    conv_kernel<<<cgrid, 128>>>(out);
}